// round 1
// baseline (speedup 1.0000x reference)
#include <cuda_runtime.h>
#include <math.h>

#define NB 8
#define IMGW 120
#define TGRID 1024
#define PPTS 1024

// scratch (no allocations allowed)
__device__ float g_h1[NB * 8 * 57 * 57];
__device__ float g_h2[NB * 10 * 26 * 26];
__device__ float g_T[NB * 12];

// ---------------- conv1 (3->8, 7x7) + maxpool2 + relu ----------------
// thread = (n, py, px) in pooled 57x57 space; computes all 8 output channels.
__global__ void conv1_kernel(const float* __restrict__ x,
                             const float* __restrict__ w,
                             const float* __restrict__ b) {
    __shared__ float ws[8 * 3 * 49];
    __shared__ float bs[8];
    for (int i = threadIdx.x; i < 8 * 3 * 49; i += blockDim.x) ws[i] = w[i];
    if (threadIdx.x < 8) bs[threadIdx.x] = b[threadIdx.x];
    __syncthreads();

    int idx = blockIdx.x * blockDim.x + threadIdx.x;
    if (idx >= NB * 57 * 57) return;
    int px = idx % 57;
    int py = (idx / 57) % 57;
    int n  = idx / (57 * 57);

    float acc[8][4];
#pragma unroll
    for (int oc = 0; oc < 8; oc++) {
        acc[oc][0] = acc[oc][1] = acc[oc][2] = acc[oc][3] = 0.f;
    }

    const float* xb = x + (size_t)n * 3 * IMGW * IMGW;
    for (int ic = 0; ic < 3; ic++) {
        const float* xc = xb + ic * IMGW * IMGW + (2 * py) * IMGW + 2 * px;
#pragma unroll
        for (int wy = 0; wy < 8; wy++) {
            float v[8];
#pragma unroll
            for (int j = 0; j < 8; j++) v[j] = __ldg(xc + wy * IMGW + j);
#pragma unroll
            for (int oc = 0; oc < 8; oc++) {
                const float* wr = ws + (oc * 3 + ic) * 49;
                if (wy < 7) {
#pragma unroll
                    for (int kx = 0; kx < 7; kx++) {
                        float wv = wr[wy * 7 + kx];
                        acc[oc][0] = fmaf(wv, v[kx], acc[oc][0]);
                        acc[oc][1] = fmaf(wv, v[kx + 1], acc[oc][1]);
                    }
                }
                if (wy >= 1) {
#pragma unroll
                    for (int kx = 0; kx < 7; kx++) {
                        float wv = wr[(wy - 1) * 7 + kx];
                        acc[oc][2] = fmaf(wv, v[kx], acc[oc][2]);
                        acc[oc][3] = fmaf(wv, v[kx + 1], acc[oc][3]);
                    }
                }
            }
        }
    }
#pragma unroll
    for (int oc = 0; oc < 8; oc++) {
        float m = fmaxf(fmaxf(acc[oc][0], acc[oc][1]), fmaxf(acc[oc][2], acc[oc][3]));
        g_h1[((n * 8 + oc) * 57 + py) * 57 + px] = fmaxf(m + bs[oc], 0.f);
    }
}

// ---------------- conv2 (8->10, 5x5) + maxpool2 + relu ----------------
// thread = (n, oc, py, px) in pooled 26x26 space.
__global__ void conv2_kernel(const float* __restrict__ w,
                             const float* __restrict__ b) {
    __shared__ float ws[10 * 8 * 25];
    __shared__ float bs[10];
    for (int i = threadIdx.x; i < 2000; i += blockDim.x) ws[i] = w[i];
    if (threadIdx.x < 10) bs[threadIdx.x] = b[threadIdx.x];
    __syncthreads();

    int idx = blockIdx.x * blockDim.x + threadIdx.x;
    if (idx >= NB * 10 * 26 * 26) return;
    int px = idx % 26;
    int py = (idx / 26) % 26;
    int oc = (idx / 676) % 10;
    int n  = idx / 6760;

    float a0 = 0.f, a1 = 0.f, a2 = 0.f, a3 = 0.f;
    for (int ic = 0; ic < 8; ic++) {
        const float* xc = g_h1 + ((n * 8 + ic) * 57 + 2 * py) * 57 + 2 * px;
        const float* wr = ws + (oc * 8 + ic) * 25;
#pragma unroll
        for (int wy = 0; wy < 6; wy++) {
            float v[6];
#pragma unroll
            for (int j = 0; j < 6; j++) v[j] = xc[wy * 57 + j];
            if (wy < 5) {
#pragma unroll
                for (int kx = 0; kx < 5; kx++) {
                    float wv = wr[wy * 5 + kx];
                    a0 = fmaf(wv, v[kx], a0);
                    a1 = fmaf(wv, v[kx + 1], a1);
                }
            }
            if (wy >= 1) {
#pragma unroll
                for (int kx = 0; kx < 5; kx++) {
                    float wv = wr[(wy - 1) * 5 + kx];
                    a2 = fmaf(wv, v[kx], a2);
                    a3 = fmaf(wv, v[kx + 1], a3);
                }
            }
        }
    }
    float m = fmaxf(fmaxf(a0, a1), fmaxf(a2, a3));
    g_h2[idx] = fmaxf(m + bs[oc], 0.f);
}

// ---------------- FC1 + FC2 + |s|*Rodrigues -> T_theta ----------------
// one block per image n, 256 threads.
__global__ void fc_kernel(const float* __restrict__ fw1, const float* __restrict__ fb1,
                          const float* __restrict__ fw2, const float* __restrict__ fb2,
                          float* __restrict__ out) {
    int n = blockIdx.x;
    int t = threadIdx.x;
    __shared__ float z[32];
    __shared__ float theta[7];

    const float* h = g_h2 + n * 6760;
    int j = t >> 3;
    int lane = t & 7;
    const float* wrow = fw1 + j * 6760;
    float s = 0.f;
    for (int k = lane; k < 6760; k += 8) s = fmaf(wrow[k], h[k], s);
#pragma unroll
    for (int off = 4; off; off >>= 1) s += __shfl_down_sync(0xffffffffu, s, off, 8);
    if (lane == 0) z[j] = fmaxf(s + fb1[j], 0.f);
    __syncthreads();

    if (t < 7) {
        float a = fb2[t];
#pragma unroll
        for (int jj = 0; jj < 32; jj++) a = fmaf(fw2[t * 32 + jj], z[jj], a);
        theta[t] = a;
    }
    __syncthreads();

    if (t == 0) {
        float s0 = fabsf(theta[0]);
        float vx = theta[1], vy = theta[2], vz = theta[3];
        float ang = sqrtf(vx * vx + vy * vy + vz * vz + 1e-8f);
        float kx = vx / ang, ky = vy / ang, kz = vz / ang;
        float sn = sinf(ang);
        float cc = 1.0f - cosf(ang);
        float K[9] = {0.f, -kz, ky,  kz, 0.f, -kx,  -ky, kx, 0.f};
        float R[9];
#pragma unroll
        for (int i = 0; i < 3; i++) {
#pragma unroll
            for (int jj = 0; jj < 3; jj++) {
                float kk = 0.f;
#pragma unroll
                for (int m = 0; m < 3; m++) kk += K[i * 3 + m] * K[m * 3 + jj];
                float r = ((i == jj) ? 1.f : 0.f) + sn * K[i * 3 + jj] + cc * kk;
                R[i * 3 + jj] = r * s0;
            }
        }
#pragma unroll
        for (int i = 0; i < 3; i++) {
#pragma unroll
            for (int jj = 0; jj < 3; jj++) {
                g_T[n * 12 + i * 4 + jj] = R[i * 3 + jj];
                out[n * 12 + i * 4 + jj] = R[i * 3 + jj];
            }
            g_T[n * 12 + i * 4 + 3] = theta[4 + i];
            out[n * 12 + i * 4 + 3] = theta[4 + i];
        }
    }
}

// ---------------- fill: aligned_x background constant ----------------
// grid=(64, 24) blocks x 256 thr; blockIdx.y = plane (n*3+c). out = d_out+96.
__global__ void fill_kernel(const float* __restrict__ x, float* __restrict__ out) {
    int plane = blockIdx.y;           // 0..23
    const float* xb = x + (size_t)plane * IMGW * IMGW;
    float cst = 0.25f * (__ldg(xb + 59 * IMGW + 59) + __ldg(xb + 59 * IMGW + 60) +
                         __ldg(xb + 60 * IMGW + 59) + __ldg(xb + 60 * IMGW + 60));
    float4 v = make_float4(cst, cst, cst, cst);
    float4* o = reinterpret_cast<float4*>(out + (size_t)plane * TGRID * TGRID);
    int stride = gridDim.x * blockDim.x;
    for (int i = blockIdx.x * blockDim.x + threadIdx.x; i < (TGRID * TGRID / 4); i += stride)
        o[i] = v;
}

// ---------------- scatter: the 1024 real sample points per image ------
__global__ void scatter_kernel(const float* __restrict__ x,
                               const float* __restrict__ uv,
                               const float* __restrict__ xyz,
                               float* __restrict__ out) {
    int idx = blockIdx.x * blockDim.x + threadIdx.x;
    if (idx >= NB * PPTS) return;
    int n = idx >> 10;
    int p = idx & 1023;

    const float* Tm = g_T + n * 12;
    float X = xyz[p * 3 + 0], Y = xyz[p * 3 + 1], Z = xyz[p * 3 + 2];
    float p0 = Tm[0] * X + Tm[1] * Y + Tm[2] * Z + Tm[3];
    float p1 = Tm[4] * X + Tm[5] * Y + Tm[6] * Z + Tm[7];

    float xs = p0 / (float)IMGW * 2.0f - 1.0f;
    float ys = -(p1 / (float)IMGW * 2.0f - 1.0f);

    float ix = ((xs + 1.0f) * (float)IMGW - 1.0f) * 0.5f;
    float iy = ((ys + 1.0f) * (float)IMGW - 1.0f) * 0.5f;

    float ix0f = floorf(ix), iy0f = floorf(iy);
    float ix1f = ix0f + 1.0f, iy1f = iy0f + 1.0f;
    float wx1 = ix - ix0f, wx0 = 1.0f - wx1;
    float wy1 = iy - iy0f, wy0 = 1.0f - wy1;

    bool vx0 = (ix0f >= 0.f) && (ix0f < (float)IMGW);
    bool vx1 = (ix1f >= 0.f) && (ix1f < (float)IMGW);
    bool vy0 = (iy0f >= 0.f) && (iy0f < (float)IMGW);
    bool vy1 = (iy1f >= 0.f) && (iy1f < (float)IMGW);

    int ii0 = (int)fminf(fmaxf(ix0f, 0.f), (float)(IMGW - 1));
    int ii1 = (int)fminf(fmaxf(ix1f, 0.f), (float)(IMGW - 1));
    int jj0 = (int)fminf(fmaxf(iy0f, 0.f), (float)(IMGW - 1));
    int jj1 = (int)fminf(fmaxf(iy1f, 0.f), (float)(IMGW - 1));

    int pxg = (int)floorf(uv[p * 2 + 0] * (float)TGRID);
    int pyg = (int)floorf(uv[p * 2 + 1] * (float)TGRID);
    if (pxg < 0 || pxg >= TGRID || pyg < 0 || pyg >= TGRID) return;  // jax scatter drops OOB

    float w00 = wy0 * wx0, w01 = wy0 * wx1, w10 = wy1 * wx0, w11 = wy1 * wx1;

#pragma unroll
    for (int c = 0; c < 3; c++) {
        const float* base = x + ((size_t)(n * 3 + c)) * IMGW * IMGW;
        float v00 = (vy0 && vx0) ? __ldg(base + jj0 * IMGW + ii0) : 0.f;
        float v01 = (vy0 && vx1) ? __ldg(base + jj0 * IMGW + ii1) : 0.f;
        float v10 = (vy1 && vx0) ? __ldg(base + jj1 * IMGW + ii0) : 0.f;
        float v11 = (vy1 && vx1) ? __ldg(base + jj1 * IMGW + ii1) : 0.f;
        float val = v00 * w00 + v01 * w01 + v10 * w10 + v11 * w11;
        out[96 + (((size_t)(n * 3 + c)) << 20) + (size_t)pxg * TGRID + pyg] = val;
    }
}

extern "C" void kernel_launch(void* const* d_in, const int* in_sizes, int n_in,
                              void* d_out, int out_size) {
    const float* x   = (const float*)d_in[0];
    const float* uv  = (const float*)d_in[1];
    const float* xyz = (const float*)d_in[2];
    const float* w1  = (const float*)d_in[3];
    const float* b1  = (const float*)d_in[4];
    const float* w2  = (const float*)d_in[5];
    const float* b2  = (const float*)d_in[6];
    const float* fw1 = (const float*)d_in[7];
    const float* fb1 = (const float*)d_in[8];
    const float* fw2 = (const float*)d_in[9];
    const float* fb2 = (const float*)d_in[10];
    float* out = (float*)d_out;

    conv1_kernel<<<(NB * 57 * 57 + 255) / 256, 256>>>(x, w1, b1);
    conv2_kernel<<<(NB * 10 * 26 * 26 + 255) / 256, 256>>>(w2, b2);
    fc_kernel<<<NB, 256>>>(fw1, fb1, fw2, fb2, out);
    dim3 fg(64, 24);
    fill_kernel<<<fg, 256>>>(x, out + 96);
    scatter_kernel<<<(NB * PPTS + 255) / 256, 256>>>(x, uv, xyz, out);
}

// round 3
// speedup vs baseline: 1.1129x; 1.1129x over previous
#include <cuda_runtime.h>
#include <math.h>

#define NB 8
#define IMGW 120
#define TGRID 1024
#define PPTS 1024

// conv1 split: 8 oc -> 2 groups of 4; NB*2*57*57 = 51984 threads
#define C1_THREADS (NB * 2 * 57 * 57)
#define C1_BLOCKS ((C1_THREADS + 255) / 256)     // 204
#define C2_THREADS (NB * 10 * 26 * 26)
#define C2_BLOCKS ((C2_THREADS + 255) / 256)     // 212
#define FILL_BLOCKS_PER_HALF 768                 // 12 planes * 64 blocks

// scratch (no allocations allowed)
__device__ float g_h1[NB * 8 * 57 * 57];
__device__ float g_h2[NB * 10 * 26 * 26];
__device__ float g_T[NB * 12];

__device__ __forceinline__ void fill_half(const float* __restrict__ x,
                                          float* __restrict__ out,
                                          int fblk, int plane_base) {
    int plane = plane_base + (fblk >> 6);        // 64 blocks per plane
    if (plane >= 24) return;
    int b = fblk & 63;
    const float* xb = x + (size_t)plane * IMGW * IMGW;
    float cst = 0.25f * (__ldg(xb + 59 * IMGW + 59) + __ldg(xb + 59 * IMGW + 60) +
                         __ldg(xb + 60 * IMGW + 59) + __ldg(xb + 60 * IMGW + 60));
    float4 v = make_float4(cst, cst, cst, cst);
    float4* o = reinterpret_cast<float4*>(out + (size_t)plane * TGRID * TGRID);
    const int stride = 64 * 256;
#pragma unroll 4
    for (int i = b * 256 + threadIdx.x; i < (TGRID * TGRID / 4); i += stride)
        o[i] = v;
}

// ---------------- kernel A: conv1 (3->8, 7x7, pool, relu) + fill planes 0-11 ----
__global__ __launch_bounds__(256) void kernelA(const float* __restrict__ x,
                                               const float* __restrict__ w,
                                               const float* __restrict__ b,
                                               float* __restrict__ out96) {
    if (blockIdx.x >= C1_BLOCKS) {
        fill_half(x, out96, blockIdx.x - C1_BLOCKS, 0);
        return;
    }

    __shared__ float ws[8 * 3 * 49];
    __shared__ float bs[8];
    for (int i = threadIdx.x; i < 8 * 3 * 49; i += blockDim.x) ws[i] = w[i];
    if (threadIdx.x < 8) bs[threadIdx.x] = b[threadIdx.x];
    __syncthreads();

    int idx = blockIdx.x * blockDim.x + threadIdx.x;
    if (idx >= C1_THREADS) return;
    int px  = idx % 57;
    int py  = (idx / 57) % 57;
    int ocg = (idx / 3249) & 1;
    int n   = idx / 6498;

    float acc[4][4];
#pragma unroll
    for (int oc = 0; oc < 4; oc++)
        acc[oc][0] = acc[oc][1] = acc[oc][2] = acc[oc][3] = 0.f;

    const float* xb = x + (size_t)n * 3 * IMGW * IMGW;
    for (int ic = 0; ic < 3; ic++) {
        const float* xc = xb + ic * IMGW * IMGW + (2 * py) * IMGW + 2 * px;
#pragma unroll
        for (int wy = 0; wy < 8; wy++) {
            float v[8];
#pragma unroll
            for (int j = 0; j < 8; j++) v[j] = __ldg(xc + wy * IMGW + j);
#pragma unroll
            for (int oc = 0; oc < 4; oc++) {
                const float* wr = ws + ((ocg * 4 + oc) * 3 + ic) * 49;
                if (wy < 7) {
#pragma unroll
                    for (int kx = 0; kx < 7; kx++) {
                        float wv = wr[wy * 7 + kx];
                        acc[oc][0] = fmaf(wv, v[kx], acc[oc][0]);
                        acc[oc][1] = fmaf(wv, v[kx + 1], acc[oc][1]);
                    }
                }
                if (wy >= 1) {
#pragma unroll
                    for (int kx = 0; kx < 7; kx++) {
                        float wv = wr[(wy - 1) * 7 + kx];
                        acc[oc][2] = fmaf(wv, v[kx], acc[oc][2]);
                        acc[oc][3] = fmaf(wv, v[kx + 1], acc[oc][3]);
                    }
                }
            }
        }
    }
#pragma unroll
    for (int oc = 0; oc < 4; oc++) {
        int woc = ocg * 4 + oc;
        float m = fmaxf(fmaxf(acc[oc][0], acc[oc][1]), fmaxf(acc[oc][2], acc[oc][3]));
        g_h1[((n * 8 + woc) * 57 + py) * 57 + px] = fmaxf(m + bs[woc], 0.f);
    }
}

// ---------------- kernel B: conv2 (8->10, 5x5, pool, relu) + fill planes 12-23 --
__global__ __launch_bounds__(256) void kernelB(const float* __restrict__ x,
                                               const float* __restrict__ w,
                                               const float* __restrict__ b,
                                               float* __restrict__ out96) {
    if (blockIdx.x >= C2_BLOCKS) {
        fill_half(x, out96, blockIdx.x - C2_BLOCKS, 12);
        return;
    }

    __shared__ float ws[10 * 8 * 25];
    __shared__ float bs[10];
    for (int i = threadIdx.x; i < 2000; i += blockDim.x) ws[i] = w[i];
    if (threadIdx.x < 10) bs[threadIdx.x] = b[threadIdx.x];
    __syncthreads();

    int idx = blockIdx.x * blockDim.x + threadIdx.x;
    if (idx >= C2_THREADS) return;
    int px = idx % 26;
    int py = (idx / 26) % 26;
    int oc = (idx / 676) % 10;
    int n  = idx / 6760;

    float a0 = 0.f, a1 = 0.f, a2 = 0.f, a3 = 0.f;
    for (int ic = 0; ic < 8; ic++) {
        const float* xc = g_h1 + ((n * 8 + ic) * 57 + 2 * py) * 57 + 2 * px;
        const float* wr = ws + (oc * 8 + ic) * 25;
#pragma unroll
        for (int wy = 0; wy < 6; wy++) {
            float v[6];
#pragma unroll
            for (int j = 0; j < 6; j++) v[j] = xc[wy * 57 + j];
            if (wy < 5) {
#pragma unroll
                for (int kx = 0; kx < 5; kx++) {
                    float wv = wr[wy * 5 + kx];
                    a0 = fmaf(wv, v[kx], a0);
                    a1 = fmaf(wv, v[kx + 1], a1);
                }
            }
            if (wy >= 1) {
#pragma unroll
                for (int kx = 0; kx < 5; kx++) {
                    float wv = wr[(wy - 1) * 5 + kx];
                    a2 = fmaf(wv, v[kx], a2);
                    a3 = fmaf(wv, v[kx + 1], a3);
                }
            }
        }
    }
    float m = fmaxf(fmaxf(a0, a1), fmaxf(a2, a3));
    g_h2[idx] = fmaxf(m + bs[oc], 0.f);
}

// ---------------- FC1 + FC2 + |s|*Rodrigues -> T_theta ----------------
__global__ __launch_bounds__(256) void fc_kernel(const float* __restrict__ fw1,
                                                 const float* __restrict__ fb1,
                                                 const float* __restrict__ fw2,
                                                 const float* __restrict__ fb2,
                                                 float* __restrict__ out) {
    int n = blockIdx.x;
    int t = threadIdx.x;
    __shared__ float z[32];
    __shared__ float theta[7];

    const float* h = g_h2 + n * 6760;
    int j = t >> 3;
    int lane = t & 7;
    const float* wrow = fw1 + j * 6760;
    float s = 0.f;
    for (int k = lane; k < 6760; k += 8) s = fmaf(wrow[k], h[k], s);
#pragma unroll
    for (int off = 4; off; off >>= 1) s += __shfl_down_sync(0xffffffffu, s, off, 8);
    if (lane == 0) z[j] = fmaxf(s + fb1[j], 0.f);
    __syncthreads();

    if (t < 7) {
        float a = fb2[t];
#pragma unroll
        for (int jj = 0; jj < 32; jj++) a = fmaf(fw2[t * 32 + jj], z[jj], a);
        theta[t] = a;
    }
    __syncthreads();

    if (t == 0) {
        float s0 = fabsf(theta[0]);
        float vx = theta[1], vy = theta[2], vz = theta[3];
        float ang = sqrtf(vx * vx + vy * vy + vz * vz + 1e-8f);
        float kx = vx / ang, ky = vy / ang, kz = vz / ang;
        float sn = sinf(ang);
        float cc = 1.0f - cosf(ang);
        float K[9] = {0.f, -kz, ky,  kz, 0.f, -kx,  -ky, kx, 0.f};
#pragma unroll
        for (int i = 0; i < 3; i++) {
#pragma unroll
            for (int jj = 0; jj < 3; jj++) {
                float kk = 0.f;
#pragma unroll
                for (int m = 0; m < 3; m++) kk += K[i * 3 + m] * K[m * 3 + jj];
                float r = (((i == jj) ? 1.f : 0.f) + sn * K[i * 3 + jj] + cc * kk) * s0;
                g_T[n * 12 + i * 4 + jj] = r;
                out[n * 12 + i * 4 + jj] = r;
            }
            g_T[n * 12 + i * 4 + 3] = theta[4 + i];
            out[n * 12 + i * 4 + 3] = theta[4 + i];
        }
    }
}

// ---------------- scatter: the 1024 real sample points per image ------
__global__ __launch_bounds__(256) void scatter_kernel(const float* __restrict__ x,
                                                      const float* __restrict__ uv,
                                                      const float* __restrict__ xyz,
                                                      float* __restrict__ out) {
    int idx = blockIdx.x * blockDim.x + threadIdx.x;
    if (idx >= NB * PPTS) return;
    int n = idx >> 10;
    int p = idx & 1023;

    const float* Tm = g_T + n * 12;
    float X = xyz[p * 3 + 0], Y = xyz[p * 3 + 1], Z = xyz[p * 3 + 2];
    float p0 = Tm[0] * X + Tm[1] * Y + Tm[2] * Z + Tm[3];
    float p1 = Tm[4] * X + Tm[5] * Y + Tm[6] * Z + Tm[7];

    float xs = p0 / (float)IMGW * 2.0f - 1.0f;
    float ys = -(p1 / (float)IMGW * 2.0f - 1.0f);

    float ix = ((xs + 1.0f) * (float)IMGW - 1.0f) * 0.5f;
    float iy = ((ys + 1.0f) * (float)IMGW - 1.0f) * 0.5f;

    float ix0f = floorf(ix), iy0f = floorf(iy);
    float ix1f = ix0f + 1.0f, iy1f = iy0f + 1.0f;
    float wx1 = ix - ix0f, wx0 = 1.0f - wx1;
    float wy1 = iy - iy0f, wy0 = 1.0f - wy1;

    bool vx0 = (ix0f >= 0.f) && (ix0f < (float)IMGW);
    bool vx1 = (ix1f >= 0.f) && (ix1f < (float)IMGW);
    bool vy0 = (iy0f >= 0.f) && (iy0f < (float)IMGW);
    bool vy1 = (iy1f >= 0.f) && (iy1f < (float)IMGW);

    int ii0 = (int)fminf(fmaxf(ix0f, 0.f), (float)(IMGW - 1));
    int ii1 = (int)fminf(fmaxf(ix1f, 0.f), (float)(IMGW - 1));
    int jj0 = (int)fminf(fmaxf(iy0f, 0.f), (float)(IMGW - 1));
    int jj1 = (int)fminf(fmaxf(iy1f, 0.f), (float)(IMGW - 1));

    int pxg = (int)floorf(uv[p * 2 + 0] * (float)TGRID);
    int pyg = (int)floorf(uv[p * 2 + 1] * (float)TGRID);
    if (pxg < 0 || pxg >= TGRID || pyg < 0 || pyg >= TGRID) return;

    float w00 = wy0 * wx0, w01 = wy0 * wx1, w10 = wy1 * wx0, w11 = wy1 * wx1;

#pragma unroll
    for (int c = 0; c < 3; c++) {
        const float* base = x + ((size_t)(n * 3 + c)) * IMGW * IMGW;
        float v00 = (vy0 && vx0) ? __ldg(base + jj0 * IMGW + ii0) : 0.f;
        float v01 = (vy0 && vx1) ? __ldg(base + jj0 * IMGW + ii1) : 0.f;
        float v10 = (vy1 && vx0) ? __ldg(base + jj1 * IMGW + ii0) : 0.f;
        float v11 = (vy1 && vx1) ? __ldg(base + jj1 * IMGW + ii1) : 0.f;
        float val = v00 * w00 + v01 * w01 + v10 * w10 + v11 * w11;
        out[96 + (((size_t)(n * 3 + c)) << 20) + (size_t)pxg * TGRID + pyg] = val;
    }
}

extern "C" void kernel_launch(void* const* d_in, const int* in_sizes, int n_in,
                              void* d_out, int out_size) {
    const float* x   = (const float*)d_in[0];
    const float* uv  = (const float*)d_in[1];
    const float* xyz = (const float*)d_in[2];
    const float* w1  = (const float*)d_in[3];
    const float* b1  = (const float*)d_in[4];
    const float* w2  = (const float*)d_in[5];
    const float* b2  = (const float*)d_in[6];
    const float* fw1 = (const float*)d_in[7];
    const float* fb1 = (const float*)d_in[8];
    const float* fw2 = (const float*)d_in[9];
    const float* fb2 = (const float*)d_in[10];
    float* out = (float*)d_out;

    kernelA<<<C1_BLOCKS + FILL_BLOCKS_PER_HALF, 256>>>(x, w1, b1, out + 96);
    kernelB<<<C2_BLOCKS + FILL_BLOCKS_PER_HALF, 256>>>(x, w2, b2, out + 96);
    fc_kernel<<<NB, 256>>>(fw1, fb1, fw2, fb2, out);
    scatter_kernel<<<(NB * PPTS + 255) / 256, 256>>>(x, uv, xyz, out);
}

// round 4
// speedup vs baseline: 1.8938x; 1.7016x over previous
#include <cuda_runtime.h>
#include <math.h>

#define NB 8
#define IMGW 120
#define TGRID 1024
#define PPTS 1024

#define C1_THREADS (NB * 2 * 57 * 57)
#define C1_BLOCKS ((C1_THREADS + 255) / 256)     // 204
#define C2_THREADS (NB * 10 * 26 * 26)
#define C2_BLOCKS ((C2_THREADS + 255) / 256)     // 212
#define FC1_BLOCKS 32

#define FILL_A (9 * 64)     // planes 0-8
#define FILL_B (9 * 64)     // planes 9-17
#define FILL_C (6 * 64)     // planes 18-23

#define H1_STRIDE 58        // padded row stride (57 cols) to keep float2 alignment

// scratch (no allocations allowed)
__device__ float g_h1[NB * 8 * 57 * H1_STRIDE];
__device__ float g_h2[NB * 10 * 26 * 26];
__device__ float g_z[NB * 32];

__device__ __forceinline__ void fill_planes(const float* __restrict__ x,
                                            float* __restrict__ out,
                                            int fblk, int plane_base) {
    int plane = plane_base + (fblk >> 6);        // 64 blocks per plane
    if (plane >= 24) return;
    int b = fblk & 63;
    const float* xb = x + (size_t)plane * IMGW * IMGW;
    float cst = 0.25f * (__ldg(xb + 59 * IMGW + 59) + __ldg(xb + 59 * IMGW + 60) +
                         __ldg(xb + 60 * IMGW + 59) + __ldg(xb + 60 * IMGW + 60));
    float4 v = make_float4(cst, cst, cst, cst);
    float4* o = reinterpret_cast<float4*>(out + (size_t)plane * TGRID * TGRID);
    const int stride = 64 * 256;
#pragma unroll 4
    for (int i = b * 256 + threadIdx.x; i < (TGRID * TGRID / 4); i += stride)
        o[i] = v;
}

// ---------------- kernel A: conv1 (3->8, 7x7, pool, relu) + fill planes 0-8 ----
__global__ __launch_bounds__(256) void kernelA(const float* __restrict__ x,
                                               const float* __restrict__ w,
                                               const float* __restrict__ b,
                                               float* __restrict__ out96) {
    if (blockIdx.x >= C1_BLOCKS) {
        fill_planes(x, out96, blockIdx.x - C1_BLOCKS, 0);
        return;
    }

    __shared__ float ws[8 * 3 * 49];
    __shared__ float bs[8];
    for (int i = threadIdx.x; i < 8 * 3 * 49; i += blockDim.x) ws[i] = w[i];
    if (threadIdx.x < 8) bs[threadIdx.x] = b[threadIdx.x];
    __syncthreads();

    int idx = blockIdx.x * blockDim.x + threadIdx.x;
    if (idx >= C1_THREADS) return;
    int px  = idx % 57;
    int py  = (idx / 57) % 57;
    int ocg = (idx / 3249) & 1;
    int n   = idx / 6498;

    float acc[4][4];
#pragma unroll
    for (int oc = 0; oc < 4; oc++)
        acc[oc][0] = acc[oc][1] = acc[oc][2] = acc[oc][3] = 0.f;

    const float* xb = x + (size_t)n * 3 * IMGW * IMGW;
    for (int ic = 0; ic < 3; ic++) {
        const float* xc = xb + ic * IMGW * IMGW + (2 * py) * IMGW + 2 * px;
#pragma unroll
        for (int wy = 0; wy < 8; wy++) {
            const float2* row = reinterpret_cast<const float2*>(xc + wy * IMGW);
            float v[8];
#pragma unroll
            for (int j = 0; j < 4; j++) {
                float2 t = __ldg(row + j);
                v[2 * j] = t.x;
                v[2 * j + 1] = t.y;
            }
#pragma unroll
            for (int oc = 0; oc < 4; oc++) {
                const float* wr = ws + ((ocg * 4 + oc) * 3 + ic) * 49;
                if (wy < 7) {
#pragma unroll
                    for (int kx = 0; kx < 7; kx++) {
                        float wv = wr[wy * 7 + kx];
                        acc[oc][0] = fmaf(wv, v[kx], acc[oc][0]);
                        acc[oc][1] = fmaf(wv, v[kx + 1], acc[oc][1]);
                    }
                }
                if (wy >= 1) {
#pragma unroll
                    for (int kx = 0; kx < 7; kx++) {
                        float wv = wr[(wy - 1) * 7 + kx];
                        acc[oc][2] = fmaf(wv, v[kx], acc[oc][2]);
                        acc[oc][3] = fmaf(wv, v[kx + 1], acc[oc][3]);
                    }
                }
            }
        }
    }
#pragma unroll
    for (int oc = 0; oc < 4; oc++) {
        int woc = ocg * 4 + oc;
        float m = fmaxf(fmaxf(acc[oc][0], acc[oc][1]), fmaxf(acc[oc][2], acc[oc][3]));
        g_h1[((n * 8 + woc) * 57 + py) * H1_STRIDE + px] = fmaxf(m + bs[woc], 0.f);
    }
}

// ---------------- kernel B: conv2 (8->10, 5x5, pool, relu) + fill planes 9-17 --
__global__ __launch_bounds__(256) void kernelB(const float* __restrict__ x,
                                               const float* __restrict__ w,
                                               const float* __restrict__ b,
                                               float* __restrict__ out96) {
    if (blockIdx.x >= C2_BLOCKS) {
        fill_planes(x, out96, blockIdx.x - C2_BLOCKS, 9);
        return;
    }

    __shared__ float ws[10 * 8 * 25];
    __shared__ float bs[10];
    for (int i = threadIdx.x; i < 2000; i += blockDim.x) ws[i] = w[i];
    if (threadIdx.x < 10) bs[threadIdx.x] = b[threadIdx.x];
    __syncthreads();

    int idx = blockIdx.x * blockDim.x + threadIdx.x;
    if (idx >= C2_THREADS) return;
    int px = idx % 26;
    int py = (idx / 26) % 26;
    int oc = (idx / 676) % 10;
    int n  = idx / 6760;

    float a0 = 0.f, a1 = 0.f, a2 = 0.f, a3 = 0.f;
    for (int ic = 0; ic < 8; ic++) {
        const float* xc = g_h1 + ((n * 8 + ic) * 57 + 2 * py) * H1_STRIDE + 2 * px;
        const float* wr = ws + (oc * 8 + ic) * 25;
#pragma unroll
        for (int wy = 0; wy < 6; wy++) {
            const float2* row = reinterpret_cast<const float2*>(xc + wy * H1_STRIDE);
            float v[6];
#pragma unroll
            for (int j = 0; j < 3; j++) {
                float2 t = row[j];
                v[2 * j] = t.x;
                v[2 * j + 1] = t.y;
            }
            if (wy < 5) {
#pragma unroll
                for (int kx = 0; kx < 5; kx++) {
                    float wv = wr[wy * 5 + kx];
                    a0 = fmaf(wv, v[kx], a0);
                    a1 = fmaf(wv, v[kx + 1], a1);
                }
            }
            if (wy >= 1) {
#pragma unroll
                for (int kx = 0; kx < 5; kx++) {
                    float wv = wr[(wy - 1) * 5 + kx];
                    a2 = fmaf(wv, v[kx], a2);
                    a3 = fmaf(wv, v[kx + 1], a3);
                }
            }
        }
    }
    float m = fmaxf(fmaxf(a0, a1), fmaxf(a2, a3));
    g_h2[idx] = fmaxf(m + bs[oc], 0.f);
}

// ---------------- kernel C: FC1 (warp per (n,j)) + fill planes 18-23 ----------
__global__ __launch_bounds__(256) void fc1_kernel(const float* __restrict__ x,
                                                  const float* __restrict__ fw1,
                                                  const float* __restrict__ fb1,
                                                  float* __restrict__ out96) {
    if (blockIdx.x >= FC1_BLOCKS) {
        fill_planes(x, out96, blockIdx.x - FC1_BLOCKS, 18);
        return;
    }
    int wid = threadIdx.x >> 5;
    int lane = threadIdx.x & 31;
    int wg = blockIdx.x * 8 + wid;       // 0..255
    int n = wg >> 5;                     // 0..7
    int j = wg & 31;                     // 0..31

    const float4* wrow = reinterpret_cast<const float4*>(fw1 + j * 6760);
    const float4* hrow = reinterpret_cast<const float4*>(g_h2 + n * 6760);
    float s = 0.f;
    // 6760 floats = 1690 float4; lane k4 = lane + 32*i, i < 53 (52*32=1664, tail 26)
#pragma unroll 4
    for (int k4 = lane; k4 < 1690; k4 += 32) {
        float4 wv = __ldg(wrow + k4);
        float4 hv = hrow[k4];
        s = fmaf(wv.x, hv.x, s);
        s = fmaf(wv.y, hv.y, s);
        s = fmaf(wv.z, hv.z, s);
        s = fmaf(wv.w, hv.w, s);
    }
#pragma unroll
    for (int off = 16; off; off >>= 1) s += __shfl_down_sync(0xffffffffu, s, off);
    if (lane == 0) g_z[n * 32 + j] = fmaxf(s + fb1[j], 0.f);
}

// ---------------- kernel D: theta/Rodrigues + scatter --------------------------
// 32 blocks: block b -> n = b>>2, quarter q = b&3 (256 points each).
__global__ __launch_bounds__(256) void scatter_kernel(const float* __restrict__ x,
                                                      const float* __restrict__ uv,
                                                      const float* __restrict__ xyz,
                                                      const float* __restrict__ fw2,
                                                      const float* __restrict__ fb2,
                                                      float* __restrict__ out) {
    int b = blockIdx.x;
    int n = b >> 2;
    int q = b & 3;
    int t = threadIdx.x;

    __shared__ float z[32];
    __shared__ float theta[7];
    __shared__ float Tm[12];

    if (t < 32) z[t] = g_z[n * 32 + t];
    __syncthreads();
    if (t < 7) {
        float a = fb2[t];
#pragma unroll
        for (int jj = 0; jj < 32; jj++) a = fmaf(fw2[t * 32 + jj], z[jj], a);
        theta[t] = a;
    }
    __syncthreads();
    if (t == 0) {
        float s0 = fabsf(theta[0]);
        float vx = theta[1], vy = theta[2], vz = theta[3];
        float ang = sqrtf(vx * vx + vy * vy + vz * vz + 1e-8f);
        float kx = vx / ang, ky = vy / ang, kz = vz / ang;
        float sn = sinf(ang);
        float cc = 1.0f - cosf(ang);
        float K[9] = {0.f, -kz, ky,  kz, 0.f, -kx,  -ky, kx, 0.f};
#pragma unroll
        for (int i = 0; i < 3; i++) {
#pragma unroll
            for (int jj = 0; jj < 3; jj++) {
                float kk = 0.f;
#pragma unroll
                for (int m = 0; m < 3; m++) kk += K[i * 3 + m] * K[m * 3 + jj];
                Tm[i * 4 + jj] = (((i == jj) ? 1.f : 0.f) + sn * K[i * 3 + jj] + cc * kk) * s0;
            }
            Tm[i * 4 + 3] = theta[4 + i];
        }
    }
    __syncthreads();

    if (q == 0 && t < 12) out[n * 12 + t] = Tm[t];

    int p = q * 256 + t;

    float X = xyz[p * 3 + 0], Y = xyz[p * 3 + 1], Z = xyz[p * 3 + 2];
    float p0 = Tm[0] * X + Tm[1] * Y + Tm[2] * Z + Tm[3];
    float p1 = Tm[4] * X + Tm[5] * Y + Tm[6] * Z + Tm[7];

    float xs = p0 / (float)IMGW * 2.0f - 1.0f;
    float ys = -(p1 / (float)IMGW * 2.0f - 1.0f);

    float ix = ((xs + 1.0f) * (float)IMGW - 1.0f) * 0.5f;
    float iy = ((ys + 1.0f) * (float)IMGW - 1.0f) * 0.5f;

    float ix0f = floorf(ix), iy0f = floorf(iy);
    float ix1f = ix0f + 1.0f, iy1f = iy0f + 1.0f;
    float wx1 = ix - ix0f, wx0 = 1.0f - wx1;
    float wy1 = iy - iy0f, wy0 = 1.0f - wy1;

    bool vx0 = (ix0f >= 0.f) && (ix0f < (float)IMGW);
    bool vx1 = (ix1f >= 0.f) && (ix1f < (float)IMGW);
    bool vy0 = (iy0f >= 0.f) && (iy0f < (float)IMGW);
    bool vy1 = (iy1f >= 0.f) && (iy1f < (float)IMGW);

    int ii0 = (int)fminf(fmaxf(ix0f, 0.f), (float)(IMGW - 1));
    int ii1 = (int)fminf(fmaxf(ix1f, 0.f), (float)(IMGW - 1));
    int jj0 = (int)fminf(fmaxf(iy0f, 0.f), (float)(IMGW - 1));
    int jj1 = (int)fminf(fmaxf(iy1f, 0.f), (float)(IMGW - 1));

    int pxg = (int)floorf(uv[p * 2 + 0] * (float)TGRID);
    int pyg = (int)floorf(uv[p * 2 + 1] * (float)TGRID);
    if (pxg < 0 || pxg >= TGRID || pyg < 0 || pyg >= TGRID) return;

    float w00 = wy0 * wx0, w01 = wy0 * wx1, w10 = wy1 * wx0, w11 = wy1 * wx1;

#pragma unroll
    for (int c = 0; c < 3; c++) {
        const float* base = x + ((size_t)(n * 3 + c)) * IMGW * IMGW;
        float v00 = (vy0 && vx0) ? __ldg(base + jj0 * IMGW + ii0) : 0.f;
        float v01 = (vy0 && vx1) ? __ldg(base + jj0 * IMGW + ii1) : 0.f;
        float v10 = (vy1 && vx0) ? __ldg(base + jj1 * IMGW + ii0) : 0.f;
        float v11 = (vy1 && vx1) ? __ldg(base + jj1 * IMGW + ii1) : 0.f;
        float val = v00 * w00 + v01 * w01 + v10 * w10 + v11 * w11;
        out[96 + (((size_t)(n * 3 + c)) << 20) + (size_t)pxg * TGRID + pyg] = val;
    }
}

extern "C" void kernel_launch(void* const* d_in, const int* in_sizes, int n_in,
                              void* d_out, int out_size) {
    const float* x   = (const float*)d_in[0];
    const float* uv  = (const float*)d_in[1];
    const float* xyz = (const float*)d_in[2];
    const float* w1  = (const float*)d_in[3];
    const float* b1  = (const float*)d_in[4];
    const float* w2  = (const float*)d_in[5];
    const float* b2  = (const float*)d_in[6];
    const float* fw1 = (const float*)d_in[7];
    const float* fb1 = (const float*)d_in[8];
    const float* fw2 = (const float*)d_in[9];
    const float* fb2 = (const float*)d_in[10];
    float* out = (float*)d_out;

    kernelA<<<C1_BLOCKS + FILL_A, 256>>>(x, w1, b1, out + 96);
    kernelB<<<C2_BLOCKS + FILL_B, 256>>>(x, w2, b2, out + 96);
    fc1_kernel<<<FC1_BLOCKS + FILL_C, 256>>>(x, fw1, fb1, out + 96);
    scatter_kernel<<<32, 256>>>(x, uv, xyz, fw2, fb2, out);
}

// round 5
// speedup vs baseline: 2.0290x; 1.0714x over previous
#include <cuda_runtime.h>
#include <math.h>

#define NB 8
#define IMGW 120
#define TGRID 1024
#define PPTS 1024

#define C1_THREADS (NB * 2 * 57 * 57)
#define C1_BLOCKS ((C1_THREADS + 255) / 256)     // 204
#define C2_THREADS (NB * 10 * 26 * 26)
#define C2_BLOCKS ((C2_THREADS + 255) / 256)     // 212

#define H1_STRIDE 58
#define PL4 (TGRID * TGRID / 4)                  // float4 per plane = 262144

// scratch (no allocations allowed)
__device__ float g_h1[NB * 8 * 57 * H1_STRIDE];
__device__ float g_h2[NB * 10 * 26 * 26];
__device__ float g_z[NB * 32];
__device__ unsigned g_bar_count;
__device__ unsigned g_bar_gen;

__device__ __forceinline__ void grid_barrier() {
    __syncthreads();
    if (threadIdx.x == 0) {
        unsigned gen = *((volatile unsigned*)&g_bar_gen);
        __threadfence();
        if (atomicAdd(&g_bar_count, 1u) == gridDim.x - 1) {
            g_bar_count = 0;
            __threadfence();
            atomicAdd(&g_bar_gen, 1u);
        } else {
            while (*((volatile unsigned*)&g_bar_gen) == gen) { __nanosleep(64); }
        }
        __threadfence();
    }
    __syncthreads();
}

__global__ __launch_bounds__(256, 2) void fused_kernel(
    const float* __restrict__ x,   const float* __restrict__ uv,
    const float* __restrict__ xyz, const float* __restrict__ w1,
    const float* __restrict__ b1,  const float* __restrict__ w2,
    const float* __restrict__ b2,  const float* __restrict__ fw1,
    const float* __restrict__ fb1, const float* __restrict__ fw2,
    const float* __restrict__ fb2, float* __restrict__ out) {

    __shared__ float s_cst[24];
    __shared__ float sh[2016];        // conv weights (phase1: 1176+8, phase2: 2000+10 -> split)
    __shared__ float sbias[10];
    __shared__ float s_small[52];     // scatter phase: z[32]+theta[7]+Tm[12]

    const int bid = blockIdx.x;
    const int tid = threadIdx.x;
    float* out96 = out + 96;
    float4* ofill = reinterpret_cast<float4*>(out96);
    const int fstride = gridDim.x * 256;

    // per-plane background constants
    if (tid < 24) {
        const float* xb = x + (size_t)tid * IMGW * IMGW;
        s_cst[tid] = 0.25f * (__ldg(xb + 59 * IMGW + 59) + __ldg(xb + 59 * IMGW + 60) +
                              __ldg(xb + 60 * IMGW + 59) + __ldg(xb + 60 * IMGW + 60));
    }

    // ================= phase 1: conv1 + fill planes 0-8 =================
    if (bid < C1_BLOCKS) {
        for (int i = tid; i < 8 * 3 * 49; i += 256) sh[i] = w1[i];
        if (tid < 8) sbias[tid] = b1[tid];
        __syncthreads();

        int idx = bid * 256 + tid;
        if (idx < C1_THREADS) {
            int px  = idx % 57;
            int py  = (idx / 57) % 57;
            int ocg = (idx / 3249) & 1;
            int n   = idx / 6498;

            float acc[4][4];
#pragma unroll
            for (int oc = 0; oc < 4; oc++)
                acc[oc][0] = acc[oc][1] = acc[oc][2] = acc[oc][3] = 0.f;

            const float* xb = x + (size_t)n * 3 * IMGW * IMGW;
            for (int ic = 0; ic < 3; ic++) {
                const float* xc = xb + ic * IMGW * IMGW + (2 * py) * IMGW + 2 * px;
#pragma unroll
                for (int wy = 0; wy < 8; wy++) {
                    const float2* row = reinterpret_cast<const float2*>(xc + wy * IMGW);
                    float v[8];
#pragma unroll
                    for (int j = 0; j < 4; j++) {
                        float2 t = __ldg(row + j);
                        v[2 * j] = t.x; v[2 * j + 1] = t.y;
                    }
#pragma unroll
                    for (int oc = 0; oc < 4; oc++) {
                        const float* wr = sh + ((ocg * 4 + oc) * 3 + ic) * 49;
                        if (wy < 7) {
#pragma unroll
                            for (int kx = 0; kx < 7; kx++) {
                                float wv = wr[wy * 7 + kx];
                                acc[oc][0] = fmaf(wv, v[kx], acc[oc][0]);
                                acc[oc][1] = fmaf(wv, v[kx + 1], acc[oc][1]);
                            }
                        }
                        if (wy >= 1) {
#pragma unroll
                            for (int kx = 0; kx < 7; kx++) {
                                float wv = wr[(wy - 1) * 7 + kx];
                                acc[oc][2] = fmaf(wv, v[kx], acc[oc][2]);
                                acc[oc][3] = fmaf(wv, v[kx + 1], acc[oc][3]);
                            }
                        }
                    }
                }
            }
#pragma unroll
            for (int oc = 0; oc < 4; oc++) {
                int woc = ocg * 4 + oc;
                float m = fmaxf(fmaxf(acc[oc][0], acc[oc][1]), fmaxf(acc[oc][2], acc[oc][3]));
                g_h1[((n * 8 + woc) * 57 + py) * H1_STRIDE + px] = fmaxf(m + sbias[woc], 0.f);
            }
        }
    }
    __syncthreads();   // s_cst ready for everyone
    for (int i = bid * 256 + tid; i < 9 * PL4; i += fstride) {
        float c = s_cst[i >> 18];
        ofill[i] = make_float4(c, c, c, c);
    }
    grid_barrier();

    // ================= phase 2: conv2 + fill planes 9-17 ================
    if (bid < C2_BLOCKS) {
        for (int i = tid; i < 2000; i += 256) sh[i] = w2[i];
        if (tid < 10) sbias[tid] = b2[tid];
        __syncthreads();

        int idx = bid * 256 + tid;
        if (idx < C2_THREADS) {
            int px = idx % 26;
            int py = (idx / 26) % 26;
            int oc = (idx / 676) % 10;
            int n  = idx / 6760;

            float a0 = 0.f, a1 = 0.f, a2 = 0.f, a3 = 0.f;
            for (int ic = 0; ic < 8; ic++) {
                const float* xc = g_h1 + ((n * 8 + ic) * 57 + 2 * py) * H1_STRIDE + 2 * px;
                const float* wr = sh + (oc * 8 + ic) * 25;
#pragma unroll
                for (int wy = 0; wy < 6; wy++) {
                    const float2* row = reinterpret_cast<const float2*>(xc + wy * H1_STRIDE);
                    float v[6];
#pragma unroll
                    for (int j = 0; j < 3; j++) {
                        float2 t = row[j];
                        v[2 * j] = t.x; v[2 * j + 1] = t.y;
                    }
                    if (wy < 5) {
#pragma unroll
                        for (int kx = 0; kx < 5; kx++) {
                            float wv = wr[wy * 5 + kx];
                            a0 = fmaf(wv, v[kx], a0);
                            a1 = fmaf(wv, v[kx + 1], a1);
                        }
                    }
                    if (wy >= 1) {
#pragma unroll
                        for (int kx = 0; kx < 5; kx++) {
                            float wv = wr[(wy - 1) * 5 + kx];
                            a2 = fmaf(wv, v[kx], a2);
                            a3 = fmaf(wv, v[kx + 1], a3);
                        }
                    }
                }
            }
            float m = fmaxf(fmaxf(a0, a1), fmaxf(a2, a3));
            g_h2[idx] = fmaxf(m + sbias[oc], 0.f);
        }
    }
    for (int i = 9 * PL4 + bid * 256 + tid; i < 18 * PL4; i += fstride) {
        float c = s_cst[i >> 18];
        ofill[i] = make_float4(c, c, c, c);
    }
    grid_barrier();

    // ================= phase 3: fc1 + fill planes 18-23 =================
    if (bid < 32) {
        int wid = tid >> 5;
        int lane = tid & 31;
        int wg = bid * 8 + wid;      // 0..255
        int n = wg >> 5;
        int j = wg & 31;

        const float4* wrow = reinterpret_cast<const float4*>(fw1 + j * 6760);
        const float4* hrow = reinterpret_cast<const float4*>(g_h2 + n * 6760);
        float s = 0.f;
#pragma unroll 4
        for (int k4 = lane; k4 < 1690; k4 += 32) {
            float4 wv = __ldg(wrow + k4);
            float4 hv = hrow[k4];
            s = fmaf(wv.x, hv.x, s);
            s = fmaf(wv.y, hv.y, s);
            s = fmaf(wv.z, hv.z, s);
            s = fmaf(wv.w, hv.w, s);
        }
#pragma unroll
        for (int off = 16; off; off >>= 1) s += __shfl_down_sync(0xffffffffu, s, off);
        if (lane == 0) g_z[n * 32 + j] = fmaxf(s + fb1[j], 0.f);
    }
    for (int i = 18 * PL4 + bid * 256 + tid; i < 24 * PL4; i += fstride) {
        float c = s_cst[i >> 18];
        ofill[i] = make_float4(c, c, c, c);
    }
    grid_barrier();

    // ================= phase 4: fc2 + Rodrigues + scatter ===============
    if (bid >= 32) return;
    {
        int n = bid >> 2;
        int q = bid & 3;
        float* z = s_small;            // 32
        float* theta = s_small + 32;   // 7
        float* Tm = s_small + 39;      // 12

        if (tid < 32) z[tid] = g_z[n * 32 + tid];
        __syncthreads();
        if (tid < 7) {
            float a = fb2[tid];
#pragma unroll
            for (int jj = 0; jj < 32; jj++) a = fmaf(fw2[tid * 32 + jj], z[jj], a);
            theta[tid] = a;
        }
        __syncthreads();
        if (tid == 0) {
            float s0 = fabsf(theta[0]);
            float vx = theta[1], vy = theta[2], vz = theta[3];
            float ang = sqrtf(vx * vx + vy * vy + vz * vz + 1e-8f);
            float kx = vx / ang, ky = vy / ang, kz = vz / ang;
            float sn = sinf(ang);
            float cc = 1.0f - cosf(ang);
            float K[9] = {0.f, -kz, ky,  kz, 0.f, -kx,  -ky, kx, 0.f};
#pragma unroll
            for (int i = 0; i < 3; i++) {
#pragma unroll
                for (int jj = 0; jj < 3; jj++) {
                    float kk = 0.f;
#pragma unroll
                    for (int m = 0; m < 3; m++) kk += K[i * 3 + m] * K[m * 3 + jj];
                    Tm[i * 4 + jj] = (((i == jj) ? 1.f : 0.f) + sn * K[i * 3 + jj] + cc * kk) * s0;
                }
                Tm[i * 4 + 3] = theta[4 + i];
            }
        }
        __syncthreads();

        if (q == 0 && tid < 12) out[n * 12 + tid] = Tm[tid];

        int p = q * 256 + tid;
        float X = xyz[p * 3 + 0], Y = xyz[p * 3 + 1], Z = xyz[p * 3 + 2];
        float p0 = Tm[0] * X + Tm[1] * Y + Tm[2] * Z + Tm[3];
        float p1 = Tm[4] * X + Tm[5] * Y + Tm[6] * Z + Tm[7];

        float xs = p0 / (float)IMGW * 2.0f - 1.0f;
        float ys = -(p1 / (float)IMGW * 2.0f - 1.0f);

        float ix = ((xs + 1.0f) * (float)IMGW - 1.0f) * 0.5f;
        float iy = ((ys + 1.0f) * (float)IMGW - 1.0f) * 0.5f;

        float ix0f = floorf(ix), iy0f = floorf(iy);
        float ix1f = ix0f + 1.0f, iy1f = iy0f + 1.0f;
        float wx1 = ix - ix0f, wx0 = 1.0f - wx1;
        float wy1 = iy - iy0f, wy0 = 1.0f - wy1;

        bool vx0 = (ix0f >= 0.f) && (ix0f < (float)IMGW);
        bool vx1 = (ix1f >= 0.f) && (ix1f < (float)IMGW);
        bool vy0 = (iy0f >= 0.f) && (iy0f < (float)IMGW);
        bool vy1 = (iy1f >= 0.f) && (iy1f < (float)IMGW);

        int ii0 = (int)fminf(fmaxf(ix0f, 0.f), (float)(IMGW - 1));
        int ii1 = (int)fminf(fmaxf(ix1f, 0.f), (float)(IMGW - 1));
        int jj0 = (int)fminf(fmaxf(iy0f, 0.f), (float)(IMGW - 1));
        int jj1 = (int)fminf(fmaxf(iy1f, 0.f), (float)(IMGW - 1));

        int pxg = (int)floorf(uv[p * 2 + 0] * (float)TGRID);
        int pyg = (int)floorf(uv[p * 2 + 1] * (float)TGRID);
        bool inb = (pxg >= 0) && (pxg < TGRID) && (pyg >= 0) && (pyg < TGRID);

        float w00 = wy0 * wx0, w01 = wy0 * wx1, w10 = wy1 * wx0, w11 = wy1 * wx1;

        if (inb) {
#pragma unroll
            for (int c = 0; c < 3; c++) {
                const float* base = x + ((size_t)(n * 3 + c)) * IMGW * IMGW;
                float v00 = (vy0 && vx0) ? __ldg(base + jj0 * IMGW + ii0) : 0.f;
                float v01 = (vy0 && vx1) ? __ldg(base + jj0 * IMGW + ii1) : 0.f;
                float v10 = (vy1 && vx0) ? __ldg(base + jj1 * IMGW + ii0) : 0.f;
                float v11 = (vy1 && vx1) ? __ldg(base + jj1 * IMGW + ii1) : 0.f;
                float val = v00 * w00 + v01 * w01 + v10 * w10 + v11 * w11;
                out[96 + (((size_t)(n * 3 + c)) << 20) + (size_t)pxg * TGRID + pyg] = val;
            }
        }
    }
}

extern "C" void kernel_launch(void* const* d_in, const int* in_sizes, int n_in,
                              void* d_out, int out_size) {
    const float* x   = (const float*)d_in[0];
    const float* uv  = (const float*)d_in[1];
    const float* xyz = (const float*)d_in[2];
    const float* w1  = (const float*)d_in[3];
    const float* b1  = (const float*)d_in[4];
    const float* w2  = (const float*)d_in[5];
    const float* b2  = (const float*)d_in[6];
    const float* fw1 = (const float*)d_in[7];
    const float* fb1 = (const float*)d_in[8];
    const float* fw2 = (const float*)d_in[9];
    const float* fb2 = (const float*)d_in[10];
    float* out = (float*)d_out;

    int dev = 0, sms = 132;
    cudaGetDevice(&dev);
    cudaDeviceGetAttribute(&sms, cudaDevAttrMultiProcessorCount, dev);
    int nblocks = 2 * sms;           // __launch_bounds__(256,2) guarantees co-residency
    if (nblocks < C2_BLOCKS) nblocks = C2_BLOCKS;  // safety: need >=212 work blocks

    fused_kernel<<<nblocks, 256>>>(x, uv, xyz, w1, b1, w2, b2,
                                   fw1, fb1, fw2, fb2, out);
}

// round 6
// speedup vs baseline: 2.0945x; 1.0323x over previous
#include <cuda_runtime.h>
#include <math.h>

#define NB 8
#define IMGW 120
#define TGRID 1024
#define PPTS 1024

// conv1: 8 oc -> 4 groups of 2
#define C1_THREADS (NB * 4 * 57 * 57)            // 103968
#define C1_BLOCKS ((C1_THREADS + 255) / 256)     // 407
#define C2_THREADS (NB * 10 * 26 * 26)
#define C2_BLOCKS ((C2_THREADS + 255) / 256)     // 212

#define H1_STRIDE 58
#define PL4 (TGRID * TGRID / 4)                  // float4 per plane = 262144

// scratch (no allocations allowed)
__device__ float g_h1[NB * 8 * 57 * H1_STRIDE];
__device__ float g_h2[NB * 10 * 26 * 26];
__device__ float g_z[NB * 32];
__device__ unsigned g_bar_count;
__device__ unsigned g_bar_gen;

__device__ __forceinline__ void grid_barrier() {
    __syncthreads();
    if (threadIdx.x == 0) {
        unsigned gen = *((volatile unsigned*)&g_bar_gen);
        __threadfence();
        if (atomicAdd(&g_bar_count, 1u) == gridDim.x - 1) {
            g_bar_count = 0;
            __threadfence();
            atomicAdd(&g_bar_gen, 1u);
        } else {
            while (*((volatile unsigned*)&g_bar_gen) == gen) { __nanosleep(64); }
        }
        __threadfence();
    }
    __syncthreads();
}

__global__ __launch_bounds__(256, 4) void fused_kernel(
    const float* __restrict__ x,   const float* __restrict__ uv,
    const float* __restrict__ xyz, const float* __restrict__ w1,
    const float* __restrict__ b1,  const float* __restrict__ w2,
    const float* __restrict__ b2,  const float* __restrict__ fw1,
    const float* __restrict__ fb1, const float* __restrict__ fw2,
    const float* __restrict__ fb2, float* __restrict__ out) {

    __shared__ float s_cst[24];
    __shared__ float sh[2016];
    __shared__ float sbias[10];
    __shared__ float s_small[52];

    const int bid = blockIdx.x;
    const int tid = threadIdx.x;
    float* out96 = out + 96;
    float4* ofill = reinterpret_cast<float4*>(out96);
    const int fstride = gridDim.x * 256;

    if (tid < 24) {
        const float* xb = x + (size_t)tid * IMGW * IMGW;
        s_cst[tid] = 0.25f * (__ldg(xb + 59 * IMGW + 59) + __ldg(xb + 59 * IMGW + 60) +
                              __ldg(xb + 60 * IMGW + 59) + __ldg(xb + 60 * IMGW + 60));
    }

    // ================= phase 1: conv1 (2 oc per thread) + fill planes 0-8 =====
    if (bid < C1_BLOCKS) {
        for (int i = tid; i < 8 * 3 * 49; i += 256) sh[i] = w1[i];
        if (tid < 8) sbias[tid] = b1[tid];
        __syncthreads();

        int idx = bid * 256 + tid;
        if (idx < C1_THREADS) {
            int px  = idx % 57;
            int py  = (idx / 57) % 57;
            int ocg = (idx / 3249) & 3;         // 4 groups of 2 oc
            int n   = idx / 12996;

            float acc[2][4];
#pragma unroll
            for (int oc = 0; oc < 2; oc++)
                acc[oc][0] = acc[oc][1] = acc[oc][2] = acc[oc][3] = 0.f;

            const float* xb = x + (size_t)n * 3 * IMGW * IMGW;
            for (int ic = 0; ic < 3; ic++) {
                const float* xc = xb + ic * IMGW * IMGW + (2 * py) * IMGW + 2 * px;
#pragma unroll
                for (int wy = 0; wy < 8; wy++) {
                    const float2* row = reinterpret_cast<const float2*>(xc + wy * IMGW);
                    float v[8];
#pragma unroll
                    for (int j = 0; j < 4; j++) {
                        float2 t = __ldg(row + j);
                        v[2 * j] = t.x; v[2 * j + 1] = t.y;
                    }
#pragma unroll
                    for (int oc = 0; oc < 2; oc++) {
                        const float* wr = sh + ((ocg * 2 + oc) * 3 + ic) * 49;
                        if (wy < 7) {
#pragma unroll
                            for (int kx = 0; kx < 7; kx++) {
                                float wv = wr[wy * 7 + kx];
                                acc[oc][0] = fmaf(wv, v[kx], acc[oc][0]);
                                acc[oc][1] = fmaf(wv, v[kx + 1], acc[oc][1]);
                            }
                        }
                        if (wy >= 1) {
#pragma unroll
                            for (int kx = 0; kx < 7; kx++) {
                                float wv = wr[(wy - 1) * 7 + kx];
                                acc[oc][2] = fmaf(wv, v[kx], acc[oc][2]);
                                acc[oc][3] = fmaf(wv, v[kx + 1], acc[oc][3]);
                            }
                        }
                    }
                }
            }
#pragma unroll
            for (int oc = 0; oc < 2; oc++) {
                int woc = ocg * 2 + oc;
                float m = fmaxf(fmaxf(acc[oc][0], acc[oc][1]), fmaxf(acc[oc][2], acc[oc][3]));
                g_h1[((n * 8 + woc) * 57 + py) * H1_STRIDE + px] = fmaxf(m + sbias[woc], 0.f);
            }
        }
    }
    __syncthreads();
    for (int i = bid * 256 + tid; i < 9 * PL4; i += fstride) {
        float c = s_cst[i >> 18];
        ofill[i] = make_float4(c, c, c, c);
    }
    grid_barrier();

    // ================= phase 2: conv2 + fill planes 9-17 ================
    if (bid < C2_BLOCKS) {
        for (int i = tid; i < 2000; i += 256) sh[i] = w2[i];
        if (tid < 10) sbias[tid] = b2[tid];
        __syncthreads();

        int idx = bid * 256 + tid;
        if (idx < C2_THREADS) {
            int px = idx % 26;
            int py = (idx / 26) % 26;
            int oc = (idx / 676) % 10;
            int n  = idx / 6760;

            float a0 = 0.f, a1 = 0.f, a2 = 0.f, a3 = 0.f;
            for (int ic = 0; ic < 8; ic++) {
                const float* xc = g_h1 + ((n * 8 + ic) * 57 + 2 * py) * H1_STRIDE + 2 * px;
                const float* wr = sh + (oc * 8 + ic) * 25;
#pragma unroll
                for (int wy = 0; wy < 6; wy++) {
                    const float2* row = reinterpret_cast<const float2*>(xc + wy * H1_STRIDE);
                    float v[6];
#pragma unroll
                    for (int j = 0; j < 3; j++) {
                        float2 t = row[j];
                        v[2 * j] = t.x; v[2 * j + 1] = t.y;
                    }
                    if (wy < 5) {
#pragma unroll
                        for (int kx = 0; kx < 5; kx++) {
                            float wv = wr[wy * 5 + kx];
                            a0 = fmaf(wv, v[kx], a0);
                            a1 = fmaf(wv, v[kx + 1], a1);
                        }
                    }
                    if (wy >= 1) {
#pragma unroll
                        for (int kx = 0; kx < 5; kx++) {
                            float wv = wr[(wy - 1) * 5 + kx];
                            a2 = fmaf(wv, v[kx], a2);
                            a3 = fmaf(wv, v[kx + 1], a3);
                        }
                    }
                }
            }
            float m = fmaxf(fmaxf(a0, a1), fmaxf(a2, a3));
            g_h2[idx] = fmaxf(m + sbias[oc], 0.f);
        }
    }
    for (int i = 9 * PL4 + bid * 256 + tid; i < 18 * PL4; i += fstride) {
        float c = s_cst[i >> 18];
        ofill[i] = make_float4(c, c, c, c);
    }
    grid_barrier();

    // ================= phase 3: fc1 + fill planes 18-23 =================
    if (bid < 32) {
        int wid = tid >> 5;
        int lane = tid & 31;
        int wg = bid * 8 + wid;
        int n = wg >> 5;
        int j = wg & 31;

        const float4* wrow = reinterpret_cast<const float4*>(fw1 + j * 6760);
        const float4* hrow = reinterpret_cast<const float4*>(g_h2 + n * 6760);
        float s = 0.f;
#pragma unroll 4
        for (int k4 = lane; k4 < 1690; k4 += 32) {
            float4 wv = __ldg(wrow + k4);
            float4 hv = hrow[k4];
            s = fmaf(wv.x, hv.x, s);
            s = fmaf(wv.y, hv.y, s);
            s = fmaf(wv.z, hv.z, s);
            s = fmaf(wv.w, hv.w, s);
        }
#pragma unroll
        for (int off = 16; off; off >>= 1) s += __shfl_down_sync(0xffffffffu, s, off);
        if (lane == 0) g_z[n * 32 + j] = fmaxf(s + fb1[j], 0.f);
    }
    for (int i = 18 * PL4 + bid * 256 + tid; i < 24 * PL4; i += fstride) {
        float c = s_cst[i >> 18];
        ofill[i] = make_float4(c, c, c, c);
    }
    grid_barrier();

    // ================= phase 4: fc2 + Rodrigues + scatter ===============
    if (bid >= 32) return;
    {
        int n = bid >> 2;
        int q = bid & 3;
        float* z = s_small;
        float* theta = s_small + 32;
        float* Tm = s_small + 39;

        if (tid < 32) z[tid] = g_z[n * 32 + tid];
        __syncthreads();
        if (tid < 7) {
            float a = fb2[tid];
#pragma unroll
            for (int jj = 0; jj < 32; jj++) a = fmaf(fw2[tid * 32 + jj], z[jj], a);
            theta[tid] = a;
        }
        __syncthreads();
        if (tid == 0) {
            float s0 = fabsf(theta[0]);
            float vx = theta[1], vy = theta[2], vz = theta[3];
            float ang = sqrtf(vx * vx + vy * vy + vz * vz + 1e-8f);
            float kx = vx / ang, ky = vy / ang, kz = vz / ang;
            float sn = sinf(ang);
            float cc = 1.0f - cosf(ang);
            float K[9] = {0.f, -kz, ky,  kz, 0.f, -kx,  -ky, kx, 0.f};
#pragma unroll
            for (int i = 0; i < 3; i++) {
#pragma unroll
                for (int jj = 0; jj < 3; jj++) {
                    float kk = 0.f;
#pragma unroll
                    for (int m = 0; m < 3; m++) kk += K[i * 3 + m] * K[m * 3 + jj];
                    Tm[i * 4 + jj] = (((i == jj) ? 1.f : 0.f) + sn * K[i * 3 + jj] + cc * kk) * s0;
                }
                Tm[i * 4 + 3] = theta[4 + i];
            }
        }
        __syncthreads();

        if (q == 0 && tid < 12) out[n * 12 + tid] = Tm[tid];

        int p = q * 256 + tid;
        float X = xyz[p * 3 + 0], Y = xyz[p * 3 + 1], Z = xyz[p * 3 + 2];
        float p0 = Tm[0] * X + Tm[1] * Y + Tm[2] * Z + Tm[3];
        float p1 = Tm[4] * X + Tm[5] * Y + Tm[6] * Z + Tm[7];

        float xs = p0 / (float)IMGW * 2.0f - 1.0f;
        float ys = -(p1 / (float)IMGW * 2.0f - 1.0f);

        float ix = ((xs + 1.0f) * (float)IMGW - 1.0f) * 0.5f;
        float iy = ((ys + 1.0f) * (float)IMGW - 1.0f) * 0.5f;

        float ix0f = floorf(ix), iy0f = floorf(iy);
        float ix1f = ix0f + 1.0f, iy1f = iy0f + 1.0f;
        float wx1 = ix - ix0f, wx0 = 1.0f - wx1;
        float wy1 = iy - iy0f, wy0 = 1.0f - wy1;

        bool vx0 = (ix0f >= 0.f) && (ix0f < (float)IMGW);
        bool vx1 = (ix1f >= 0.f) && (ix1f < (float)IMGW);
        bool vy0 = (iy0f >= 0.f) && (iy0f < (float)IMGW);
        bool vy1 = (iy1f >= 0.f) && (iy1f < (float)IMGW);

        int ii0 = (int)fminf(fmaxf(ix0f, 0.f), (float)(IMGW - 1));
        int ii1 = (int)fminf(fmaxf(ix1f, 0.f), (float)(IMGW - 1));
        int jj0 = (int)fminf(fmaxf(iy0f, 0.f), (float)(IMGW - 1));
        int jj1 = (int)fminf(fmaxf(iy1f, 0.f), (float)(IMGW - 1));

        int pxg = (int)floorf(uv[p * 2 + 0] * (float)TGRID);
        int pyg = (int)floorf(uv[p * 2 + 1] * (float)TGRID);
        bool inb = (pxg >= 0) && (pxg < TGRID) && (pyg >= 0) && (pyg < TGRID);

        float w00 = wy0 * wx0, w01 = wy0 * wx1, w10 = wy1 * wx0, w11 = wy1 * wx1;

        if (inb) {
#pragma unroll
            for (int c = 0; c < 3; c++) {
                const float* base = x + ((size_t)(n * 3 + c)) * IMGW * IMGW;
                float v00 = (vy0 && vx0) ? __ldg(base + jj0 * IMGW + ii0) : 0.f;
                float v01 = (vy0 && vx1) ? __ldg(base + jj0 * IMGW + ii1) : 0.f;
                float v10 = (vy1 && vx0) ? __ldg(base + jj1 * IMGW + ii0) : 0.f;
                float v11 = (vy1 && vx1) ? __ldg(base + jj1 * IMGW + ii1) : 0.f;
                float val = v00 * w00 + v01 * w01 + v10 * w10 + v11 * w11;
                out[96 + (((size_t)(n * 3 + c)) << 20) + (size_t)pxg * TGRID + pyg] = val;
            }
        }
    }
}

extern "C" void kernel_launch(void* const* d_in, const int* in_sizes, int n_in,
                              void* d_out, int out_size) {
    const float* x   = (const float*)d_in[0];
    const float* uv  = (const float*)d_in[1];
    const float* xyz = (const float*)d_in[2];
    const float* w1  = (const float*)d_in[3];
    const float* b1  = (const float*)d_in[4];
    const float* w2  = (const float*)d_in[5];
    const float* b2  = (const float*)d_in[6];
    const float* fw1 = (const float*)d_in[7];
    const float* fb1 = (const float*)d_in[8];
    const float* fw2 = (const float*)d_in[9];
    const float* fb2 = (const float*)d_in[10];
    float* out = (float*)d_out;

    int dev = 0, sms = 148;
    cudaGetDevice(&dev);
    cudaDeviceGetAttribute(&sms, cudaDevAttrMultiProcessorCount, dev);
    int nblocks = 4 * sms;                        // __launch_bounds__(256,4) co-residency
    if (nblocks < C1_BLOCKS) nblocks = C1_BLOCKS; // need >= 407 work blocks

    fused_kernel<<<nblocks, 256>>>(x, uv, xyz, w1, b1, w2, b2,
                                   fw1, fb1, fw2, fb2, out);
}